// round 1
// baseline (speedup 1.0000x reference)
#include <cuda_runtime.h>
#include <cuda_bf16.h>

// Problem constants (reference fixes E=1,600,000, N=50,000; caps add headroom)
#define NHEADS 4
#define HIDDEN 64
#define TEMP 0.125f   // 64^-0.5

#define E_CAP 1700000
#define N_CAP 65600

// Scratch (no cudaMalloc allowed)
__device__ float g_scores[E_CAP * NHEADS];   // leakyrelu'd scores per edge/head
__device__ int   g_counts[N_CAP + 1];
__device__ int   g_offsets[N_CAP + 1];
__device__ int   g_cursor[N_CAP];
__device__ int   g_edge_ids[E_CAP];

// ---------------------------------------------------------------------------
// K0: zero the histogram
__global__ void zero_counts_kernel(int n) {
    int i = blockIdx.x * blockDim.x + threadIdx.x;
    if (i <= n) g_counts[i] = 0;
}

// ---------------------------------------------------------------------------
// K1: per-edge scores + degree histogram.
// 8 lanes per edge; each lane loads 8 floats (2x float4) of q and k.
// Lane j covers floats [8j, 8j+8) => half of head j/2. shfl_xor(1) pairs halves.
__global__ void scores_kernel(const float* __restrict__ keys,
                              const float* __restrict__ queries,
                              const int*   __restrict__ dst,
                              int E) {
    int gid  = blockIdx.x * blockDim.x + threadIdx.x;
    int edge = gid >> 3;
    int sub  = gid & 7;
    bool ok  = (edge < E);

    float partial = 0.0f;
    int d = 0;
    if (ok) {
        const float4* q4 = reinterpret_cast<const float4*>(queries + (size_t)edge * HIDDEN + sub * 8);
        const float4* k4 = reinterpret_cast<const float4*>(keys    + (size_t)edge * HIDDEN + sub * 8);
        float4 a0 = q4[0], a1 = q4[1];
        float4 b0 = k4[0], b1 = k4[1];
        partial = a0.x * b0.x + a0.y * b0.y + a0.z * b0.z + a0.w * b0.w
                + a1.x * b1.x + a1.y * b1.y + a1.z * b1.z + a1.w * b1.w;
        d = dst[edge];
    }
    // pair halves of each head (lanes 2h, 2h+1)
    partial += __shfl_xor_sync(0xffffffffu, partial, 1);

    if (ok && ((sub & 1) == 0)) {
        int h = sub >> 1;
        float s = partial * TEMP;
        s = (s >= 0.0f) ? s : 0.2f * s;           // LeakyReLU(0.2)
        g_scores[(size_t)edge * NHEADS + h] = s;
    }
    if (ok && sub == 0) atomicAdd(&g_counts[d], 1);
}

// ---------------------------------------------------------------------------
// K2: single-block exclusive scan of counts -> offsets (+ cursor copy).
__global__ void scan_kernel(int n) {
    __shared__ int sh_warp[32];
    __shared__ int sh_carry;
    const int tid  = threadIdx.x;
    const int lane = tid & 31;
    const int wid  = tid >> 5;
    if (tid == 0) sh_carry = 0;
    __syncthreads();

    for (int base = 0; base < n; base += 1024) {
        int idx = base + tid;
        int v = (idx < n) ? g_counts[idx] : 0;
        int x = v;
#pragma unroll
        for (int dd = 1; dd < 32; dd <<= 1) {
            int y = __shfl_up_sync(0xffffffffu, x, dd);
            if (lane >= dd) x += y;
        }
        if (lane == 31) sh_warp[wid] = x;
        __syncthreads();
        if (wid == 0) {
            int s = sh_warp[lane];
#pragma unroll
            for (int dd = 1; dd < 32; dd <<= 1) {
                int y = __shfl_up_sync(0xffffffffu, s, dd);
                if (lane >= dd) s += y;
            }
            sh_warp[lane] = s;
        }
        __syncthreads();
        int carry = sh_carry;
        int woff  = (wid > 0) ? sh_warp[wid - 1] : 0;
        int incl  = x + woff + carry;
        if (idx < n) {
            int excl = incl - v;
            g_offsets[idx] = excl;
            g_cursor[idx]  = excl;
            if (idx == n - 1) g_offsets[n] = incl;
        }
        __syncthreads();                 // everyone done reading sh_carry/sh_warp
        if (tid == 1023) sh_carry = incl;
        __syncthreads();
    }
}

// ---------------------------------------------------------------------------
// K3: scatter edge ids into CSR order
__global__ void scatter_kernel(const int* __restrict__ dst, int E) {
    int e = blockIdx.x * blockDim.x + threadIdx.x;
    if (e >= E) return;
    int d = dst[e];
    int pos = atomicAdd(&g_cursor[d], 1);
    g_edge_ids[pos] = e;
}

// ---------------------------------------------------------------------------
// K4: warp-per-node gather.
// Phase A: segment max (lanes parallel over edges, float4 scores).
// Phase B: segment exp-sum.
// Phase C: sequential over edges; 32 lanes cover the 64 features (2 each),
//          V loads coalesced 2x128B per edge; out written once.
__global__ void gather_kernel(const float* __restrict__ values,
                              const float* __restrict__ bias,
                              const float* __restrict__ mask,
                              float* __restrict__ out,
                              int n_nodes) {
    const int warps_per_block = blockDim.x >> 5;
    const int node = blockIdx.x * warps_per_block + (threadIdx.x >> 5);
    const int lane = threadIdx.x & 31;
    if (node >= n_nodes) return;

    const int start = g_offsets[node];
    const int end   = g_offsets[node + 1];
    const float4* sc4 = reinterpret_cast<const float4*>(g_scores);

    // ---- Phase A: max over edges, per head
    float4 m = make_float4(-3.4e38f, -3.4e38f, -3.4e38f, -3.4e38f);
    for (int i = start + lane; i < end; i += 32) {
        int e = g_edge_ids[i];
        float4 s = sc4[e];
        m.x = fmaxf(m.x, s.x); m.y = fmaxf(m.y, s.y);
        m.z = fmaxf(m.z, s.z); m.w = fmaxf(m.w, s.w);
    }
#pragma unroll
    for (int off = 16; off > 0; off >>= 1) {
        m.x = fmaxf(m.x, __shfl_xor_sync(0xffffffffu, m.x, off));
        m.y = fmaxf(m.y, __shfl_xor_sync(0xffffffffu, m.y, off));
        m.z = fmaxf(m.z, __shfl_xor_sync(0xffffffffu, m.z, off));
        m.w = fmaxf(m.w, __shfl_xor_sync(0xffffffffu, m.w, off));
    }

    // ---- Phase B: exp-sum
    float4 dsum = make_float4(0.f, 0.f, 0.f, 0.f);
    for (int i = start + lane; i < end; i += 32) {
        int e = g_edge_ids[i];
        float4 s = sc4[e];
        dsum.x += __expf(s.x - m.x);
        dsum.y += __expf(s.y - m.y);
        dsum.z += __expf(s.z - m.z);
        dsum.w += __expf(s.w - m.w);
    }
#pragma unroll
    for (int off = 16; off > 0; off >>= 1) {
        dsum.x += __shfl_xor_sync(0xffffffffu, dsum.x, off);
        dsum.y += __shfl_xor_sync(0xffffffffu, dsum.y, off);
        dsum.z += __shfl_xor_sync(0xffffffffu, dsum.z, off);
        dsum.w += __shfl_xor_sync(0xffffffffu, dsum.w, off);
    }

    // per-lane head assignment: feature f0 = lane (head h0 = lane/16 in {0,1}),
    //                            feature f1 = lane+32 (head h1 = 2 + lane/16)
    const int hsel = lane >> 4;            // 0 or 1
    const float m0 = hsel ? m.y : m.x;
    const float m1 = hsel ? m.w : m.z;
    const float id0 = 1.0f / (hsel ? dsum.y : dsum.x);
    const float id1 = 1.0f / (hsel ? dsum.w : dsum.z);
    const int h0 = hsel;          // 0/1
    const int h1 = 2 + hsel;      // 2/3

    // ---- Phase C: weighted accumulation of V
    float acc0 = 0.0f, acc1 = 0.0f;
    for (int i = start; i < end; ++i) {
        int e = g_edge_ids[i];   // same for all lanes -> broadcast
        size_t eb = (size_t)e * NHEADS;
        float s0 = g_scores[eb + h0];
        float s1 = g_scores[eb + h1];
        float mk = mask[e];
        float w0 = (__expf(s0 - m0) * id0 + bias[eb + h0]) * mk;
        float w1 = (__expf(s1 - m1) * id1 + bias[eb + h1]) * mk;
        const float* vrow = values + (size_t)e * HIDDEN;
        acc0 = fmaf(w0, vrow[lane],      acc0);
        acc1 = fmaf(w1, vrow[lane + 32], acc1);
    }
    out[(size_t)node * HIDDEN + lane]      = acc0;
    out[(size_t)node * HIDDEN + lane + 32] = acc1;
}

// ---------------------------------------------------------------------------
extern "C" void kernel_launch(void* const* d_in, const int* in_sizes, int n_in,
                              void* d_out, int out_size) {
    const float* keys    = (const float*)d_in[0];
    const float* queries = (const float*)d_in[1];
    const float* values  = (const float*)d_in[2];
    const float* bias    = (const float*)d_in[3];
    const float* mask    = (const float*)d_in[4];
    const int*   dst     = (const int*)d_in[5];
    float* out = (float*)d_out;

    const int E = in_sizes[0] / HIDDEN;
    const int N = out_size / HIDDEN;

    // K0: zero histogram
    zero_counts_kernel<<<(N + 256) / 256, 256>>>(N);
    // K1: scores + histogram (8 lanes per edge)
    {
        long long threads = (long long)E * 8;
        int blocks = (int)((threads + 255) / 256);
        scores_kernel<<<blocks, 256>>>(keys, queries, dst, E);
    }
    // K2: scan
    scan_kernel<<<1, 1024>>>(N);
    // K3: scatter edge ids
    scatter_kernel<<<(E + 255) / 256, 256>>>(dst, E);
    // K4: gather (1 warp per node, 8 warps per block)
    gather_kernel<<<(N + 7) / 8, 256>>>(values, bias, mask, out, N);
}

// round 2
// speedup vs baseline: 1.1395x; 1.1395x over previous
#include <cuda_runtime.h>
#include <cuda_bf16.h>

#define NHEADS 4
#define HIDDEN 64
#define TEMP 0.125f   // 64^-0.5

#define E_CAP 1700000
#define N_CAP 65600

// Scratch (no cudaMalloc allowed)
__device__ float g_scores[E_CAP * NHEADS];   // leakyrelu'd scores per edge/head
__device__ int   g_counts[N_CAP + 1];
__device__ int   g_offsets[N_CAP + 1];
__device__ int   g_cursor[N_CAP];
__device__ int   g_edge_ids[E_CAP + 64];

// ---------------------------------------------------------------------------
// K0: zero the histogram
__global__ void zero_counts_kernel(int n) {
    int i = blockIdx.x * blockDim.x + threadIdx.x;
    if (i <= n) g_counts[i] = 0;
}

// ---------------------------------------------------------------------------
// K1: per-edge scores + degree histogram.
// 8 lanes per edge; each lane loads 8 floats (2x float4) of q and k.
__global__ void scores_kernel(const float* __restrict__ keys,
                              const float* __restrict__ queries,
                              const int*   __restrict__ dst,
                              int E) {
    int gid  = blockIdx.x * blockDim.x + threadIdx.x;
    int edge = gid >> 3;
    int sub  = gid & 7;
    bool ok  = (edge < E);

    float partial = 0.0f;
    int d = 0;
    if (ok) {
        const float4* q4 = reinterpret_cast<const float4*>(queries + (size_t)edge * HIDDEN + sub * 8);
        const float4* k4 = reinterpret_cast<const float4*>(keys    + (size_t)edge * HIDDEN + sub * 8);
        float4 a0 = q4[0], a1 = q4[1];
        float4 b0 = k4[0], b1 = k4[1];
        partial = a0.x * b0.x + a0.y * b0.y + a0.z * b0.z + a0.w * b0.w
                + a1.x * b1.x + a1.y * b1.y + a1.z * b1.z + a1.w * b1.w;
        d = dst[edge];
    }
    partial += __shfl_xor_sync(0xffffffffu, partial, 1);

    if (ok && ((sub & 1) == 0)) {
        int h = sub >> 1;
        float s = partial * TEMP;
        s = (s >= 0.0f) ? s : 0.2f * s;           // LeakyReLU(0.2)
        g_scores[(size_t)edge * NHEADS + h] = s;
    }
    if (ok && sub == 0) atomicAdd(&g_counts[d], 1);
}

// ---------------------------------------------------------------------------
// K2: single-block exclusive scan of counts -> offsets (+ cursor copy).
__global__ void scan_kernel(int n) {
    __shared__ int sh_warp[32];
    __shared__ int sh_carry;
    const int tid  = threadIdx.x;
    const int lane = tid & 31;
    const int wid  = tid >> 5;
    if (tid == 0) sh_carry = 0;
    __syncthreads();

    for (int base = 0; base < n; base += 1024) {
        int idx = base + tid;
        int v = (idx < n) ? g_counts[idx] : 0;
        int x = v;
#pragma unroll
        for (int dd = 1; dd < 32; dd <<= 1) {
            int y = __shfl_up_sync(0xffffffffu, x, dd);
            if (lane >= dd) x += y;
        }
        if (lane == 31) sh_warp[wid] = x;
        __syncthreads();
        if (wid == 0) {
            int s = sh_warp[lane];
#pragma unroll
            for (int dd = 1; dd < 32; dd <<= 1) {
                int y = __shfl_up_sync(0xffffffffu, s, dd);
                if (lane >= dd) s += y;
            }
            sh_warp[lane] = s;
        }
        __syncthreads();
        int carry = sh_carry;
        int woff  = (wid > 0) ? sh_warp[wid - 1] : 0;
        int incl  = x + woff + carry;
        if (idx < n) {
            int excl = incl - v;
            g_offsets[idx] = excl;
            g_cursor[idx]  = excl;
            if (idx == n - 1) g_offsets[n] = incl;
        }
        __syncthreads();
        if (tid == 1023) sh_carry = incl;
        __syncthreads();
    }
}

// ---------------------------------------------------------------------------
// K3: scatter edge ids into CSR order. 4 edges per thread for atomic MLP.
__global__ void scatter_kernel(const int* __restrict__ dst, int E) {
    int base = (blockIdx.x * blockDim.x + threadIdx.x) * 4;
#pragma unroll
    for (int k = 0; k < 4; ++k) {
        int e = base + k;
        if (e < E) {
            int d = dst[e];
            int pos = atomicAdd(&g_cursor[d], 1);
            g_edge_ids[pos] = e;
        }
    }
}

// ---------------------------------------------------------------------------
// K4: warp-per-node gather.
// Phase A: segment max (lane-parallel).
// Phase B: segment exp-sum (lane-parallel).
// Phase C: lane-parallel weight computation (4 exps/lane/chunk), then an
//          unrolled inner loop broadcasting weights via shfl and doing
//          coalesced V loads (2x128B per edge).
__global__ void gather_kernel(const float* __restrict__ values,
                              const float* __restrict__ bias,
                              const float* __restrict__ mask,
                              float* __restrict__ out,
                              int n_nodes) {
    const int node = blockIdx.x * (blockDim.x >> 5) + (threadIdx.x >> 5);
    const int lane = threadIdx.x & 31;
    if (node >= n_nodes) return;

    const int start = g_offsets[node];
    const int end   = g_offsets[node + 1];
    const float4* sc4 = reinterpret_cast<const float4*>(g_scores);
    const float4* b4  = reinterpret_cast<const float4*>(bias);

    // ---- Phase A: max over edges, per head
    float4 m = make_float4(-3.4e38f, -3.4e38f, -3.4e38f, -3.4e38f);
    for (int i = start + lane; i < end; i += 32) {
        int e = g_edge_ids[i];
        float4 s = sc4[e];
        m.x = fmaxf(m.x, s.x); m.y = fmaxf(m.y, s.y);
        m.z = fmaxf(m.z, s.z); m.w = fmaxf(m.w, s.w);
    }
#pragma unroll
    for (int off = 16; off > 0; off >>= 1) {
        m.x = fmaxf(m.x, __shfl_xor_sync(0xffffffffu, m.x, off));
        m.y = fmaxf(m.y, __shfl_xor_sync(0xffffffffu, m.y, off));
        m.z = fmaxf(m.z, __shfl_xor_sync(0xffffffffu, m.z, off));
        m.w = fmaxf(m.w, __shfl_xor_sync(0xffffffffu, m.w, off));
    }

    // ---- Phase B: exp-sum
    float4 dsum = make_float4(0.f, 0.f, 0.f, 0.f);
    for (int i = start + lane; i < end; i += 32) {
        int e = g_edge_ids[i];
        float4 s = sc4[e];
        dsum.x += __expf(s.x - m.x);
        dsum.y += __expf(s.y - m.y);
        dsum.z += __expf(s.z - m.z);
        dsum.w += __expf(s.w - m.w);
    }
#pragma unroll
    for (int off = 16; off > 0; off >>= 1) {
        dsum.x += __shfl_xor_sync(0xffffffffu, dsum.x, off);
        dsum.y += __shfl_xor_sync(0xffffffffu, dsum.y, off);
        dsum.z += __shfl_xor_sync(0xffffffffu, dsum.z, off);
        dsum.w += __shfl_xor_sync(0xffffffffu, dsum.w, off);
    }
    float4 inv;
    inv.x = 1.0f / dsum.x; inv.y = 1.0f / dsum.y;
    inv.z = 1.0f / dsum.z; inv.w = 1.0f / dsum.w;

    const int hsel = lane >> 4;   // consumer head select: 0 or 1

    // ---- Phase C: chunked lane-parallel weights + shfl-broadcast V loop
    float acc0 = 0.0f, acc1 = 0.0f;
    for (int base = start; base < end; base += 32) {
        const int cnt = min(32, end - base);
        int e = 0;
        float4 wv = make_float4(0.f, 0.f, 0.f, 0.f);
        if (lane < cnt) {
            e = g_edge_ids[base + lane];
            float4 s = sc4[e];
            float4 b = b4[e];
            float mk = mask[e];
            wv.x = (__expf(s.x - m.x) * inv.x + b.x) * mk;
            wv.y = (__expf(s.y - m.y) * inv.y + b.y) * mk;
            wv.z = (__expf(s.z - m.z) * inv.z + b.z) * mk;
            wv.w = (__expf(s.w - m.w) * inv.w + b.w) * mk;
        }
#pragma unroll 4
        for (int j = 0; j < cnt; ++j) {
            int   ej = __shfl_sync(0xffffffffu, e,    j);
            float wx = __shfl_sync(0xffffffffu, wv.x, j);
            float wy = __shfl_sync(0xffffffffu, wv.y, j);
            float wz = __shfl_sync(0xffffffffu, wv.z, j);
            float ww = __shfl_sync(0xffffffffu, wv.w, j);
            float w0 = hsel ? wy : wx;
            float w1 = hsel ? ww : wz;
            const float* vrow = values + (size_t)ej * HIDDEN;
            acc0 = fmaf(w0, vrow[lane],      acc0);
            acc1 = fmaf(w1, vrow[lane + 32], acc1);
        }
    }
    out[(size_t)node * HIDDEN + lane]      = acc0;
    out[(size_t)node * HIDDEN + lane + 32] = acc1;
}

// ---------------------------------------------------------------------------
extern "C" void kernel_launch(void* const* d_in, const int* in_sizes, int n_in,
                              void* d_out, int out_size) {
    const float* keys    = (const float*)d_in[0];
    const float* queries = (const float*)d_in[1];
    const float* values  = (const float*)d_in[2];
    const float* bias    = (const float*)d_in[3];
    const float* mask    = (const float*)d_in[4];
    const int*   dst     = (const int*)d_in[5];
    float* out = (float*)d_out;

    const int E = in_sizes[0] / HIDDEN;
    const int N = out_size / HIDDEN;

    zero_counts_kernel<<<(N + 256) / 256, 256>>>(N);
    {
        long long threads = (long long)E * 8;
        int blocks = (int)((threads + 255) / 256);
        scores_kernel<<<blocks, 256>>>(keys, queries, dst, E);
    }
    scan_kernel<<<1, 1024>>>(N);
    scatter_kernel<<<(E + 1023) / 1024, 256>>>(dst, E);
    gather_kernel<<<(N + 7) / 8, 256>>>(values, bias, mask, out, N);
}

// round 3
// speedup vs baseline: 1.1626x; 1.0203x over previous
#include <cuda_runtime.h>
#include <cuda_bf16.h>

#define NHEADS 4
#define HIDDEN 64
#define TEMP 0.125f   // 64^-0.5

#define E_CAP 1700000
#define N_CAP 65600

// Scratch (no cudaMalloc allowed)
// g_pack[2e]   = {s0,s1,s2,s3}            (leaky-relu'd scores)
// g_pack[2e+1] = {b0*mk, b1*mk, b2*mk, b3*mk}
__device__ float4 g_pack[2 * E_CAP];
__device__ int    g_counts[N_CAP + 1];
__device__ int    g_offsets[N_CAP + 1];
__device__ int    g_cursor[N_CAP];
__device__ int2   g_elist[E_CAP + 64];     // {edge_id, mask_bits} in CSR order

// ---------------------------------------------------------------------------
__global__ void zero_counts_kernel(int n) {
    int i = blockIdx.x * blockDim.x + threadIdx.x;
    if (i <= n) g_counts[i] = 0;
}

// ---------------------------------------------------------------------------
// K1: per-edge scores + packed record + degree histogram.
// 8 lanes per edge. sub==0 writes packed scores + histogram; sub==1 writes
// bias*mask (coalesced reads: edges are consecutive within the warp).
__global__ void scores_kernel(const float* __restrict__ keys,
                              const float* __restrict__ queries,
                              const float* __restrict__ bias,
                              const float* __restrict__ mask,
                              const int*   __restrict__ dst,
                              int E) {
    const int gid  = blockIdx.x * blockDim.x + threadIdx.x;
    const int edge = gid >> 3;
    const int sub  = gid & 7;
    const int lane = threadIdx.x & 31;
    const bool ok  = (edge < E);

    float partial = 0.0f;
    if (ok) {
        const float4* q4 = reinterpret_cast<const float4*>(queries + (size_t)edge * HIDDEN + sub * 8);
        const float4* k4 = reinterpret_cast<const float4*>(keys    + (size_t)edge * HIDDEN + sub * 8);
        float4 a0 = q4[0], a1 = q4[1];
        float4 b0 = k4[0], b1 = k4[1];
        partial = a0.x * b0.x + a0.y * b0.y + a0.z * b0.z + a0.w * b0.w
                + a1.x * b1.x + a1.y * b1.y + a1.z * b1.z + a1.w * b1.w;
    }
    partial += __shfl_xor_sync(0xffffffffu, partial, 1);   // head h at sub 2h

    const int base = lane & ~7;
    float s1 = __shfl_sync(0xffffffffu, partial, base | 2);
    float s2 = __shfl_sync(0xffffffffu, partial, base | 4);
    float s3 = __shfl_sync(0xffffffffu, partial, base | 6);

    if (ok && sub == 0) {
        float4 sv;
        float v0 = partial * TEMP, v1 = s1 * TEMP, v2 = s2 * TEMP, v3 = s3 * TEMP;
        sv.x = (v0 >= 0.0f) ? v0 : 0.2f * v0;
        sv.y = (v1 >= 0.0f) ? v1 : 0.2f * v1;
        sv.z = (v2 >= 0.0f) ? v2 : 0.2f * v2;
        sv.w = (v3 >= 0.0f) ? v3 : 0.2f * v3;
        g_pack[2 * (size_t)edge] = sv;
        atomicAdd(&g_counts[dst[edge]], 1);
    }
    if (ok && sub == 1) {
        const float4 b = reinterpret_cast<const float4*>(bias)[edge];
        const float mk = mask[edge];
        g_pack[2 * (size_t)edge + 1] = make_float4(b.x * mk, b.y * mk, b.z * mk, b.w * mk);
    }
}

// ---------------------------------------------------------------------------
// K2: single-block exclusive scan of counts -> offsets (+ cursor copy).
__global__ void scan_kernel(int n) {
    __shared__ int sh_warp[32];
    __shared__ int sh_carry;
    const int tid  = threadIdx.x;
    const int lane = tid & 31;
    const int wid  = tid >> 5;
    if (tid == 0) sh_carry = 0;
    __syncthreads();

    for (int base = 0; base < n; base += 1024) {
        int idx = base + tid;
        int v = (idx < n) ? g_counts[idx] : 0;
        int x = v;
#pragma unroll
        for (int dd = 1; dd < 32; dd <<= 1) {
            int y = __shfl_up_sync(0xffffffffu, x, dd);
            if (lane >= dd) x += y;
        }
        if (lane == 31) sh_warp[wid] = x;
        __syncthreads();
        if (wid == 0) {
            int s = sh_warp[lane];
#pragma unroll
            for (int dd = 1; dd < 32; dd <<= 1) {
                int y = __shfl_up_sync(0xffffffffu, s, dd);
                if (lane >= dd) s += y;
            }
            sh_warp[lane] = s;
        }
        __syncthreads();
        int carry = sh_carry;
        int woff  = (wid > 0) ? sh_warp[wid - 1] : 0;
        int incl  = x + woff + carry;
        if (idx < n) {
            int excl = incl - v;
            g_offsets[idx] = excl;
            g_cursor[idx]  = excl;
            if (idx == n - 1) g_offsets[n] = incl;
        }
        __syncthreads();
        if (tid == 1023) sh_carry = incl;
        __syncthreads();
    }
}

// ---------------------------------------------------------------------------
// K3: scatter {edge_id, mask} into CSR order.
__global__ void scatter_kernel(const int* __restrict__ dst,
                               const float* __restrict__ mask,
                               int E) {
    int base = (blockIdx.x * blockDim.x + threadIdx.x) * 4;
#pragma unroll
    for (int k = 0; k < 4; ++k) {
        int e = base + k;
        if (e < E) {
            int d = dst[e];
            float mk = mask[e];
            int pos = atomicAdd(&g_cursor[d], 1);
            g_elist[pos] = make_int2(e, __float_as_int(mk));
        }
    }
}

// ---------------------------------------------------------------------------
// K4: warp-per-node gather.
// One random 32B sector per edge (packed scores+bias*mask), L1-resident
// across the three phases. V loads coalesced (2x128B per edge).
__global__ void gather_kernel(const float* __restrict__ values,
                              float* __restrict__ out,
                              int n_nodes) {
    const int node = blockIdx.x * (blockDim.x >> 5) + (threadIdx.x >> 5);
    const int lane = threadIdx.x & 31;
    if (node >= n_nodes) return;

    const int start = g_offsets[node];
    const int end   = g_offsets[node + 1];

    // ---- Phase A: max over edges, per head
    float4 m = make_float4(-3.4e38f, -3.4e38f, -3.4e38f, -3.4e38f);
    for (int i = start + lane; i < end; i += 32) {
        float4 s = g_pack[2 * (size_t)g_elist[i].x];
        m.x = fmaxf(m.x, s.x); m.y = fmaxf(m.y, s.y);
        m.z = fmaxf(m.z, s.z); m.w = fmaxf(m.w, s.w);
    }
#pragma unroll
    for (int off = 16; off > 0; off >>= 1) {
        m.x = fmaxf(m.x, __shfl_xor_sync(0xffffffffu, m.x, off));
        m.y = fmaxf(m.y, __shfl_xor_sync(0xffffffffu, m.y, off));
        m.z = fmaxf(m.z, __shfl_xor_sync(0xffffffffu, m.z, off));
        m.w = fmaxf(m.w, __shfl_xor_sync(0xffffffffu, m.w, off));
    }

    // ---- Phase B: exp-sum (pack re-read hits L1)
    float4 dsum = make_float4(0.f, 0.f, 0.f, 0.f);
    for (int i = start + lane; i < end; i += 32) {
        float4 s = g_pack[2 * (size_t)g_elist[i].x];
        dsum.x += __expf(s.x - m.x);
        dsum.y += __expf(s.y - m.y);
        dsum.z += __expf(s.z - m.z);
        dsum.w += __expf(s.w - m.w);
    }
#pragma unroll
    for (int off = 16; off > 0; off >>= 1) {
        dsum.x += __shfl_xor_sync(0xffffffffu, dsum.x, off);
        dsum.y += __shfl_xor_sync(0xffffffffu, dsum.y, off);
        dsum.z += __shfl_xor_sync(0xffffffffu, dsum.z, off);
        dsum.w += __shfl_xor_sync(0xffffffffu, dsum.w, off);
    }
    float4 inv;
    inv.x = 1.0f / dsum.x; inv.y = 1.0f / dsum.y;
    inv.z = 1.0f / dsum.z; inv.w = 1.0f / dsum.w;

    const int hsel = lane >> 4;   // consumer head select: 0 or 1

    // ---- Phase C: lane-parallel weights + shfl-broadcast V accumulation
    float acc0 = 0.0f, acc1 = 0.0f;
    for (int base = start; base < end; base += 32) {
        const int cnt = min(32, end - base);
        int e = 0;
        float4 wv = make_float4(0.f, 0.f, 0.f, 0.f);
        if (lane < cnt) {
            int2 r = g_elist[base + lane];
            e = r.x;
            float mk = __int_as_float(r.y);
            float4 s  = g_pack[2 * (size_t)e];
            float4 bm = g_pack[2 * (size_t)e + 1];
            wv.x = __expf(s.x - m.x) * inv.x * mk + bm.x;
            wv.y = __expf(s.y - m.y) * inv.y * mk + bm.y;
            wv.z = __expf(s.z - m.z) * inv.z * mk + bm.z;
            wv.w = __expf(s.w - m.w) * inv.w * mk + bm.w;
        }
#pragma unroll 4
        for (int j = 0; j < cnt; ++j) {
            int   ej = __shfl_sync(0xffffffffu, e,    j);
            float wx = __shfl_sync(0xffffffffu, wv.x, j);
            float wy = __shfl_sync(0xffffffffu, wv.y, j);
            float wz = __shfl_sync(0xffffffffu, wv.z, j);
            float ww = __shfl_sync(0xffffffffu, wv.w, j);
            float w0 = hsel ? wy : wx;
            float w1 = hsel ? ww : wz;
            const float* vrow = values + (size_t)ej * HIDDEN;
            acc0 = fmaf(w0, vrow[lane],      acc0);
            acc1 = fmaf(w1, vrow[lane + 32], acc1);
        }
    }
    out[(size_t)node * HIDDEN + lane]      = acc0;
    out[(size_t)node * HIDDEN + lane + 32] = acc1;
}

// ---------------------------------------------------------------------------
extern "C" void kernel_launch(void* const* d_in, const int* in_sizes, int n_in,
                              void* d_out, int out_size) {
    const float* keys    = (const float*)d_in[0];
    const float* queries = (const float*)d_in[1];
    const float* values  = (const float*)d_in[2];
    const float* bias    = (const float*)d_in[3];
    const float* mask    = (const float*)d_in[4];
    const int*   dst     = (const int*)d_in[5];
    float* out = (float*)d_out;

    const int E = in_sizes[0] / HIDDEN;
    const int N = out_size / HIDDEN;

    zero_counts_kernel<<<(N + 256) / 256, 256>>>(N);
    {
        long long threads = (long long)E * 8;
        int blocks = (int)((threads + 255) / 256);
        scores_kernel<<<blocks, 256>>>(keys, queries, bias, mask, dst, E);
    }
    scan_kernel<<<1, 1024>>>(N);
    scatter_kernel<<<(E + 1023) / 1024, 256>>>(dst, mask, E);
    gather_kernel<<<(N + 7) / 8, 256>>>(values, out, N);
}